// round 13
// baseline (speedup 1.0000x reference)
#include <cuda_runtime.h>
#include <math.h>

#define NUM_BLOCKS 1184
#define NUM_THREADS 256
#define CHUNK_F4 4096LL   // float4 per chunk per input (64 KB per input)

__device__ float g_partials[NUM_BLOCKS];
__device__ unsigned int g_ticket;   // zero-init; reset by last block each run
__device__ unsigned int g_chunk;    // zero-init; reset by last block each run

__global__ __launch_bounds__(NUM_THREADS)
void lik_steal_cs4_kernel(const float* __restrict__ o,
                          const float* __restrict__ x,
                          const float* __restrict__ noise_p,
                          float* __restrict__ out,
                          long long n4, double nd)
{
    const float4* __restrict__ o4 = (const float4*)o;
    const float4* __restrict__ x4 = (const float4*)x;

    __shared__ long long s_base[2];
    int lane = threadIdx.x & 31;
    int wid  = threadIdx.x >> 5;

    if (threadIdx.x == 0)
        s_base[0] = (long long)atomicAdd(&g_chunk, 1u) * CHUNK_F4;
    __syncthreads();

    float acc = 0.0f;
    int parity = 0;

    while (true) {
        long long base = s_base[parity];
        // Prefetch next chunk base — atomic latency hidden under this chunk's loads
        if (threadIdx.x == 0)
            s_base[parity ^ 1] = (long long)atomicAdd(&g_chunk, 1u) * CHUNK_F4;
        if (base >= n4) break;

        if (base + CHUNK_F4 <= n4) {
            // full 64KB-per-input chunk: four passes of 4 float4 per thread per input
            #pragma unroll
            for (int q = 0; q < 4; q++) {
                long long i0 = base + q * 1024 + threadIdx.x;
                float4 a0 = __ldcs(&o4[i0]);
                float4 b0 = __ldcs(&x4[i0]);
                float4 a1 = __ldcs(&o4[i0 + 256]);
                float4 b1 = __ldcs(&x4[i0 + 256]);
                float4 a2 = __ldcs(&o4[i0 + 512]);
                float4 b2 = __ldcs(&x4[i0 + 512]);
                float4 a3 = __ldcs(&o4[i0 + 768]);
                float4 b3 = __ldcs(&x4[i0 + 768]);
                float d;
                d = a0.x - b0.x; acc = fmaf(d, d, acc);
                d = a0.y - b0.y; acc = fmaf(d, d, acc);
                d = a0.z - b0.z; acc = fmaf(d, d, acc);
                d = a0.w - b0.w; acc = fmaf(d, d, acc);
                d = a1.x - b1.x; acc = fmaf(d, d, acc);
                d = a1.y - b1.y; acc = fmaf(d, d, acc);
                d = a1.z - b1.z; acc = fmaf(d, d, acc);
                d = a1.w - b1.w; acc = fmaf(d, d, acc);
                d = a2.x - b2.x; acc = fmaf(d, d, acc);
                d = a2.y - b2.y; acc = fmaf(d, d, acc);
                d = a2.z - b2.z; acc = fmaf(d, d, acc);
                d = a2.w - b2.w; acc = fmaf(d, d, acc);
                d = a3.x - b3.x; acc = fmaf(d, d, acc);
                d = a3.y - b3.y; acc = fmaf(d, d, acc);
                d = a3.z - b3.z; acc = fmaf(d, d, acc);
                d = a3.w - b3.w; acc = fmaf(d, d, acc);
            }
        } else {
            // ragged tail chunk
            for (long long i = base + threadIdx.x; i < n4; i += NUM_THREADS) {
                float4 a = __ldcs(&o4[i]);
                float4 b = __ldcs(&x4[i]);
                float d;
                d = a.x - b.x; acc = fmaf(d, d, acc);
                d = a.y - b.y; acc = fmaf(d, d, acc);
                d = a.z - b.z; acc = fmaf(d, d, acc);
                d = a.w - b.w; acc = fmaf(d, d, acc);
            }
        }
        __syncthreads();   // next-base write visible; safe to flip
        parity ^= 1;
    }

    // intra-block reduce
    #pragma unroll
    for (int off = 16; off > 0; off >>= 1)
        acc += __shfl_xor_sync(0xFFFFFFFFu, acc, off);

    __shared__ float warp_sums[NUM_THREADS / 32];
    if (lane == 0) warp_sums[wid] = acc;
    __syncthreads();

    __shared__ bool s_is_last;
    if (threadIdx.x == 0) {
        float v = 0.0f;
        #pragma unroll
        for (int w = 0; w < NUM_THREADS / 32; w++) v += warp_sums[w];
        g_partials[blockIdx.x] = v;
        __threadfence();
        unsigned int t = atomicAdd(&g_ticket, 1u);
        s_is_last = (t == (unsigned int)(gridDim.x - 1));
    }
    __syncthreads();

    if (!s_is_last) return;

    // Last block: sum partials (hot in L2), finalize in double, reset counters.
    __shared__ double s_sums[NUM_THREADS / 32];
    double s = 0.0;
    for (int k = threadIdx.x; k < NUM_BLOCKS; k += NUM_THREADS)
        s += (double)g_partials[k];

    #pragma unroll
    for (int off = 16; off > 0; off >>= 1)
        s += __shfl_xor_sync(0xFFFFFFFFu, s, off);
    if (lane == 0) s_sums[wid] = s;
    __syncthreads();

    if (wid == 0) {
        double v = (lane < NUM_THREADS / 32) ? s_sums[lane] : 0.0;
        #pragma unroll
        for (int off = 4; off > 0; off >>= 1)
            v += __shfl_xor_sync(0xFFFFFFFFu, v, off);
        if (lane == 0) {
            const double LOG_2PI = 1.8378770664093453;
            double noise = (double)noise_p[0];
            double result = -0.5 * nd * LOG_2PI
                          - 0.5 * nd * noise
                          - 0.5 * exp(-2.0 * noise) * v;
            out[0] = (float)result;
            g_ticket = 0u;   // reset for next graph replay
            g_chunk  = 0u;
        }
    }
}

extern "C" void kernel_launch(void* const* d_in, const int* in_sizes, int n_in,
                              void* d_out, int out_size)
{
    const float* o     = (const float*)d_in[0];
    const float* x     = (const float*)d_in[1];
    const float* noise = (const float*)d_in[2];
    float* out = (float*)d_out;

    long long n  = (long long)in_sizes[0];
    long long n4 = n >> 2;

    lik_steal_cs4_kernel<<<NUM_BLOCKS, NUM_THREADS>>>(o, x, noise, out, n4, (double)n);
}